// round 1
// baseline (speedup 1.0000x reference)
#include <cuda_runtime.h>
#include <math.h>

// ----------------------------------------------------------------------------
// LinearAttentionBlock: out = ((phi(xWq+bq) @ phi(xWk+bk)^T masked) @ (xWv+bv))
//                              / rowsum  @ Wo + bo
// B=4, N=2048, d_model=1024, d_inner=2048. All fp32.
// Decomposition: 3 proj GEMMs -> masked NT GEMM (lower-tri only) -> rowsum ->
//                truncated NN GEMM with divide epilogue -> output GEMM.
// ----------------------------------------------------------------------------

#define BM 128
#define BN 128
#define BK 16
#define TM 8
#define TN 8

#define BATCH 4
#define SEQ   2048
#define DM    1024
#define DI    2048

// Scratch (allocation-free rule: __device__ globals)
__device__ __align__(16) float g_Q[BATCH * SEQ * DI];
__device__ __align__(16) float g_K[BATCH * SEQ * DI];
__device__ __align__(16) float g_V[BATCH * SEQ * DI];
__device__ __align__(16) float g_S[BATCH * SEQ * SEQ];
__device__ __align__(16) float g_O[BATCH * SEQ * DI];
__device__ __align__(16) float g_den[BATCH * SEQ];

__device__ __forceinline__ float phi_act(float v) {
    // elu(v) + 1:  v>0 -> v+1 ; else exp(v)
    return v > 0.f ? v + 1.f : __expf(v);
}

// ---------------------------------------------------------------------------
// Generic NN SGEMM: C[M,N] = A[M,K] @ B[K,N] + bias[N], optional phi epilogue.
// Requires M%128==0, N%128==0, K%16==0. 256 threads, 8x8 per thread.
// ---------------------------------------------------------------------------
template <int ACT>
__global__ __launch_bounds__(256) void sgemm_nn(
    const float* __restrict__ A, const float* __restrict__ B,
    const float* __restrict__ bias, float* __restrict__ C,
    int M, int N, int K)
{
    __shared__ float As[BK][BM];
    __shared__ float Bs[BK][BN];
    const int tid = threadIdx.x;
    const int tx = tid & 15;
    const int ty = tid >> 4;
    const int rowBase = blockIdx.y * BM;
    const int colBase = blockIdx.x * BN;

    float acc[TM][TN];
#pragma unroll
    for (int i = 0; i < TM; i++)
#pragma unroll
        for (int j = 0; j < TN; j++) acc[i][j] = 0.f;

    for (int kt = 0; kt < K; kt += BK) {
#pragma unroll
        for (int l = 0; l < 2; l++) {
            int i = tid + l * 256;           // 512 float4 for A tile
            int r = i >> 2;
            int c4 = (i & 3) * 4;
            float4 f = *(const float4*)(A + (size_t)(rowBase + r) * K + kt + c4);
            As[c4 + 0][r] = f.x; As[c4 + 1][r] = f.y;
            As[c4 + 2][r] = f.z; As[c4 + 3][r] = f.w;
        }
#pragma unroll
        for (int l = 0; l < 2; l++) {
            int i = tid + l * 256;           // 512 float4 for B tile
            int r = i >> 5;
            int c4 = (i & 31) * 4;
            *(float4*)&Bs[r][c4] =
                *(const float4*)(B + (size_t)(kt + r) * N + colBase + c4);
        }
        __syncthreads();
#pragma unroll
        for (int k = 0; k < BK; k++) {
            float a[TM], b[TN];
#pragma unroll
            for (int i = 0; i < TM; i++) a[i] = As[k][ty * TM + i];
#pragma unroll
            for (int j = 0; j < TN; j++) b[j] = Bs[k][tx * TN + j];
#pragma unroll
            for (int i = 0; i < TM; i++)
#pragma unroll
                for (int j = 0; j < TN; j++)
                    acc[i][j] = fmaf(a[i], b[j], acc[i][j]);
        }
        __syncthreads();
    }

#pragma unroll
    for (int i = 0; i < TM; i++) {
        int row = rowBase + ty * TM + i;
#pragma unroll
        for (int j = 0; j < TN; j++) {
            int col = colBase + tx * TN + j;
            float v = acc[i][j] + bias[col];
            if (ACT == 1) v = phi_act(v);
            C[(size_t)row * N + col] = v;
        }
    }
}

// ---------------------------------------------------------------------------
// Scores: S[b][n][m] = sum_d Q[b][n][d]*K[b][m][d], m<=n only (causal).
// NT GEMM per batch. Upper-triangle blocks skipped entirely (never read later).
// Diagonal block masked to exact 0 above the diagonal.
// ---------------------------------------------------------------------------
__global__ __launch_bounds__(256) void sgemm_nt_scores(
    const float* __restrict__ Qg, const float* __restrict__ Kg,
    float* __restrict__ Sg)
{
    const int bx = blockIdx.x;   // key block (m)
    const int by = blockIdx.y;   // query block (n)
    if (bx > by) return;         // strictly upper: never written, never read
    const int b = blockIdx.z;

    const float* A = Qg + (size_t)b * SEQ * DI;
    const float* B = Kg + (size_t)b * SEQ * DI;
    float* C = Sg + (size_t)b * SEQ * SEQ;

    __shared__ float As[BK][BM];
    __shared__ float Bs[BK][BN];
    const int tid = threadIdx.x;
    const int tx = tid & 15;
    const int ty = tid >> 4;
    const int rowBase = by * BM;
    const int colBase = bx * BN;

    float acc[TM][TN];
#pragma unroll
    for (int i = 0; i < TM; i++)
#pragma unroll
        for (int j = 0; j < TN; j++) acc[i][j] = 0.f;

    for (int kt = 0; kt < DI; kt += BK) {
#pragma unroll
        for (int l = 0; l < 2; l++) {
            int i = tid + l * 256;
            int r = i >> 2;
            int c4 = (i & 3) * 4;
            float4 f = *(const float4*)(A + (size_t)(rowBase + r) * DI + kt + c4);
            As[c4 + 0][r] = f.x; As[c4 + 1][r] = f.y;
            As[c4 + 2][r] = f.z; As[c4 + 3][r] = f.w;
        }
#pragma unroll
        for (int l = 0; l < 2; l++) {
            int i = tid + l * 256;           // key row = colBase+mm, dim = kt+d4
            int mm = i >> 2;
            int d4 = (i & 3) * 4;
            float4 f = *(const float4*)(B + (size_t)(colBase + mm) * DI + kt + d4);
            Bs[d4 + 0][mm] = f.x; Bs[d4 + 1][mm] = f.y;
            Bs[d4 + 2][mm] = f.z; Bs[d4 + 3][mm] = f.w;
        }
        __syncthreads();
#pragma unroll
        for (int k = 0; k < BK; k++) {
            float a[TM], bb[TN];
#pragma unroll
            for (int i = 0; i < TM; i++) a[i] = As[k][ty * TM + i];
#pragma unroll
            for (int j = 0; j < TN; j++) bb[j] = Bs[k][tx * TN + j];
#pragma unroll
            for (int i = 0; i < TM; i++)
#pragma unroll
                for (int j = 0; j < TN; j++)
                    acc[i][j] = fmaf(a[i], bb[j], acc[i][j]);
        }
        __syncthreads();
    }

    const bool diag = (bx == by);
#pragma unroll
    for (int i = 0; i < TM; i++) {
        int row = rowBase + ty * TM + i;
#pragma unroll
        for (int j = 0; j < TN; j++) {
            int col = colBase + tx * TN + j;
            float v = acc[i][j];
            if (diag && col > row) v = 0.f;
            C[(size_t)row * SEQ + col] = v;
        }
    }
}

// ---------------------------------------------------------------------------
// Denominator: den[b][n] = EPS + sum_{m written} S[b][n][m]
// (upper part of diagonal block is exact 0, so summing the written region
//  [0, (n/128+1)*128) equals the masked sum). One 256-thread block per row.
// ---------------------------------------------------------------------------
__global__ __launch_bounds__(256) void rowsum_k(
    const float* __restrict__ Sg, float* __restrict__ den)
{
    const int row = blockIdx.x;          // 0 .. BATCH*SEQ-1
    const int b = row >> 11;
    const int n = row & (SEQ - 1);
    const float* sr = Sg + ((size_t)b * SEQ + n) * SEQ;
    const int mlim = ((n >> 7) + 1) << 7;

    float s = 0.f;
    for (int m = threadIdx.x; m < mlim; m += 256) s += sr[m];

    __shared__ float red[256];
    red[threadIdx.x] = s;
    __syncthreads();
#pragma unroll
    for (int o = 128; o > 0; o >>= 1) {
        if (threadIdx.x < o) red[threadIdx.x] += red[threadIdx.x + o];
        __syncthreads();
    }
    if (threadIdx.x == 0) den[row] = red[0] + 1e-6f;
}

// ---------------------------------------------------------------------------
// O[b] = (S[b] @ V[b]) / den[b][row].  K-loop truncated at the diagonal:
// for query block by, only m < (by+1)*128 can be nonzero.
// ---------------------------------------------------------------------------
__global__ __launch_bounds__(256) void sgemm_av(
    const float* __restrict__ Sg, const float* __restrict__ Vg,
    const float* __restrict__ den, float* __restrict__ Og)
{
    const int b = blockIdx.z;
    const float* A = Sg + (size_t)b * SEQ * SEQ;
    const float* B = Vg + (size_t)b * SEQ * DI;
    float* C = Og + (size_t)b * SEQ * DI;

    __shared__ float As[BK][BM];
    __shared__ float Bs[BK][BN];
    const int tid = threadIdx.x;
    const int tx = tid & 15;
    const int ty = tid >> 4;
    const int rowBase = blockIdx.y * BM;
    const int colBase = blockIdx.x * BN;
    const int Klim = (blockIdx.y + 1) * BM;   // causal truncation

    float acc[TM][TN];
#pragma unroll
    for (int i = 0; i < TM; i++)
#pragma unroll
        for (int j = 0; j < TN; j++) acc[i][j] = 0.f;

    for (int kt = 0; kt < Klim; kt += BK) {
#pragma unroll
        for (int l = 0; l < 2; l++) {
            int i = tid + l * 256;
            int r = i >> 2;
            int c4 = (i & 3) * 4;
            float4 f = *(const float4*)(A + (size_t)(rowBase + r) * SEQ + kt + c4);
            As[c4 + 0][r] = f.x; As[c4 + 1][r] = f.y;
            As[c4 + 2][r] = f.z; As[c4 + 3][r] = f.w;
        }
#pragma unroll
        for (int l = 0; l < 2; l++) {
            int i = tid + l * 256;
            int r = i >> 5;
            int c4 = (i & 31) * 4;
            *(float4*)&Bs[r][c4] =
                *(const float4*)(B + (size_t)(kt + r) * DI + colBase + c4);
        }
        __syncthreads();
#pragma unroll
        for (int k = 0; k < BK; k++) {
            float a[TM], bb[TN];
#pragma unroll
            for (int i = 0; i < TM; i++) a[i] = As[k][ty * TM + i];
#pragma unroll
            for (int j = 0; j < TN; j++) bb[j] = Bs[k][tx * TN + j];
#pragma unroll
            for (int i = 0; i < TM; i++)
#pragma unroll
                for (int j = 0; j < TN; j++)
                    acc[i][j] = fmaf(a[i], bb[j], acc[i][j]);
        }
        __syncthreads();
    }

#pragma unroll
    for (int i = 0; i < TM; i++) {
        int row = rowBase + ty * TM + i;
        float inv = 1.f / den[b * SEQ + row];
#pragma unroll
        for (int j = 0; j < TN; j++) {
            int col = colBase + tx * TN + j;
            C[(size_t)row * DI + col] = acc[i][j] * inv;
        }
    }
}

// ---------------------------------------------------------------------------
extern "C" void kernel_launch(void* const* d_in, const int* in_sizes, int n_in,
                              void* d_out, int out_size)
{
    const float* x  = (const float*)d_in[0];
    const float* Wq = (const float*)d_in[1];
    const float* bq = (const float*)d_in[2];
    const float* Wk = (const float*)d_in[3];
    const float* bk = (const float*)d_in[4];
    const float* Wv = (const float*)d_in[5];
    const float* bv = (const float*)d_in[6];
    const float* Wo = (const float*)d_in[7];
    const float* bo = (const float*)d_in[8];
    float* out = (float*)d_out;

    float *Qp, *Kp, *Vp, *Sp, *Op, *dp;
    cudaGetSymbolAddress((void**)&Qp, g_Q);
    cudaGetSymbolAddress((void**)&Kp, g_K);
    cudaGetSymbolAddress((void**)&Vp, g_V);
    cudaGetSymbolAddress((void**)&Sp, g_S);
    cudaGetSymbolAddress((void**)&Op, g_O);
    cudaGetSymbolAddress((void**)&dp, g_den);

    const int M = BATCH * SEQ;                 // 8192

    // Q/K/V projections (fused bias + phi for Q,K)
    dim3 gproj(DI / BN, M / BM);               // (16, 64)
    sgemm_nn<1><<<gproj, 256>>>(x, Wq, bq, Qp, M, DI, DM);
    sgemm_nn<1><<<gproj, 256>>>(x, Wk, bk, Kp, M, DI, DM);
    sgemm_nn<0><<<gproj, 256>>>(x, Wv, bv, Vp, M, DI, DM);

    // Causal scores (lower-triangle blocks only)
    dim3 gsc(SEQ / BN, SEQ / BM, BATCH);       // (16, 16, 4)
    sgemm_nt_scores<<<gsc, 256>>>(Qp, Kp, Sp);

    // Denominators
    rowsum_k<<<BATCH * SEQ, 256>>>(Sp, dp);

    // (S @ V) / den
    dim3 gav(DI / BN, SEQ / BM, BATCH);        // (16, 16, 4)
    sgemm_av<<<gav, 256>>>(Sp, Vp, dp, Op);

    // Output projection
    dim3 gout(DM / BN, M / BM);                // (8, 64)
    sgemm_nn<0><<<gout, 256>>>(Op, Wo, bo, out, M, DM, DI);
}